// round 1
// baseline (speedup 1.0000x reference)
#include <cuda_runtime.h>

#define NROWS 100000
#define D 128
#define KN 16

// Scratch (no allocations allowed): two [N,128] buffers + score vectors.
__device__ float g_hid[NROWS * D];   // GEMM output of current layer
__device__ float g_h1[NROWS * D];    // layer-1 activation (input to layer 2)
__device__ float g_sin[NROWS];
__device__ float g_sout[NROWS];

// ---------------------------------------------------------------------------
// GEMM: hid = X @ W, X:[N,128], W:[128,128].
// Block: 32 rows x 128 cols, 128 threads. Thread: 8 rows x 4 cols.
// Per k-step/thread: 8 broadcast LDS + 1 LDG.128 (L1-resident W) + 32 FFMA.
// ---------------------------------------------------------------------------
__global__ __launch_bounds__(128) void gemm_k(const float* __restrict__ X,
                                              const float* __restrict__ W,
                                              float* __restrict__ hid) {
    __shared__ float xs[32][D];
    const int tx = threadIdx.x;
    const int row0 = blockIdx.x * 32;

    // Load x tile: 32*128 floats = 1024 float4, 8 per thread, coalesced.
    const float4* xsrc = (const float4*)(X + (size_t)row0 * D);
    float4* xdst = (float4*)xs;
#pragma unroll
    for (int i = 0; i < 8; i++) xdst[tx + i * 128] = xsrc[tx + i * 128];
    __syncthreads();

    const int rg = tx >> 5;   // warp id 0..3 -> rows rg*8..rg*8+7
    const int cg = tx & 31;   // cols cg*4..cg*4+3

    float acc[8][4];
#pragma unroll
    for (int r = 0; r < 8; r++)
#pragma unroll
        for (int j = 0; j < 4; j++) acc[r][j] = 0.f;

    const float4* W4 = (const float4*)W;
#pragma unroll 4
    for (int k = 0; k < D; k++) {
        float4 w = W4[k * 32 + cg];
#pragma unroll
        for (int r = 0; r < 8; r++) {
            float xv = xs[rg * 8 + r][k];   // broadcast within warp
            acc[r][0] += xv * w.x;
            acc[r][1] += xv * w.y;
            acc[r][2] += xv * w.z;
            acc[r][3] += xv * w.w;
        }
    }

    float4* hid4 = (float4*)hid;
#pragma unroll
    for (int r = 0; r < 8; r++) {
        float4 o = make_float4(acc[r][0], acc[r][1], acc[r][2], acc[r][3]);
        hid4[(size_t)(row0 + rg * 8 + r) * 32 + cg] = o;
    }
}

// ---------------------------------------------------------------------------
// Per-row attention score dots: sin[i] = hid[i]·a_in, sout[i] = hid[i]·a_out.
// One warp per row, float4 per lane, shuffle reduce.
// ---------------------------------------------------------------------------
__global__ __launch_bounds__(256) void scores_k(const float* __restrict__ hid,
                                                const float* __restrict__ a_in,
                                                const float* __restrict__ a_out,
                                                float* __restrict__ sin_,
                                                float* __restrict__ sout_) {
    int gid = blockIdx.x * blockDim.x + threadIdx.x;
    int row = gid >> 5;
    int lane = gid & 31;
    if (row >= NROWS) return;
    float4 h = ((const float4*)(hid + (size_t)row * D))[lane];
    float4 ai = ((const float4*)a_in)[lane];
    float4 ao = ((const float4*)a_out)[lane];
    float si = h.x * ai.x + h.y * ai.y + h.z * ai.z + h.w * ai.w;
    float so = h.x * ao.x + h.y * ao.y + h.z * ao.z + h.w * ao.w;
#pragma unroll
    for (int o = 16; o; o >>= 1) {
        si += __shfl_xor_sync(0xffffffffu, si, o);
        so += __shfl_xor_sync(0xffffffffu, so, o);
    }
    if (lane == 0) { sin_[row] = si; sout_[row] = so; }
}

// ---------------------------------------------------------------------------
// Attention softmax (K=16) + weighted neighbor aggregation + bias + ReLU.
// One block (128 threads) per destination row; lanes 0..15 do the softmax.
// ---------------------------------------------------------------------------
__global__ __launch_bounds__(128) void agg_k(const float* __restrict__ hid,
                                             const float* __restrict__ sin_,
                                             const float* __restrict__ sout_,
                                             const int* __restrict__ dst,
                                             const float* __restrict__ adj,
                                             const float* __restrict__ b,
                                             float* __restrict__ out) {
    const int i = blockIdx.x;
    const int c = threadIdx.x;
    __shared__ float watt[KN];
    __shared__ int ds[KN];

    if (c < KN) {
        int d = dst[i * KN + c];
        ds[c] = d;
        float e = sin_[i] + sout_[d];
        e = e > 0.f ? e : 0.2f * e;              // leaky_relu(0.2)
        float m = e;
#pragma unroll
        for (int o = 8; o; o >>= 1)
            m = fmaxf(m, __shfl_xor_sync(0xffffu, m, o, 16));
        float ex = __expf(e - m);
        float s = ex;
#pragma unroll
        for (int o = 8; o; o >>= 1)
            s += __shfl_xor_sync(0xffffu, s, o, 16);
        watt[c] = adj[i * KN + c] * (ex / s);
    }
    __syncthreads();

    float acc = b[c];
#pragma unroll
    for (int k = 0; k < KN; k++)
        acc += watt[k] * hid[(size_t)ds[k] * D + c];   // coalesced 512B row gather
    out[(size_t)i * D + c] = fmaxf(acc, 0.f);          // layer ReLU
}

// ---------------------------------------------------------------------------

extern "C" void kernel_launch(void* const* d_in, const int* in_sizes, int n_in,
                              void* d_out, int out_size) {
    const float* x     = (const float*)d_in[0];
    const int*   dst   = (const int*)  d_in[1];
    const float* adj   = (const float*)d_in[2];
    const float* w1    = (const float*)d_in[3];
    const float* ain1  = (const float*)d_in[4];
    const float* aout1 = (const float*)d_in[5];
    const float* b1    = (const float*)d_in[6];
    const float* w2    = (const float*)d_in[7];
    const float* ain2  = (const float*)d_in[8];
    const float* aout2 = (const float*)d_in[9];
    const float* b2    = (const float*)d_in[10];
    float* out = (float*)d_out;

    float *hid, *h1, *sin_, *sout_;
    cudaGetSymbolAddress((void**)&hid,   g_hid);
    cudaGetSymbolAddress((void**)&h1,    g_h1);
    cudaGetSymbolAddress((void**)&sin_,  g_sin);
    cudaGetSymbolAddress((void**)&sout_, g_sout);

    const int gemm_grid = NROWS / 32;              // 3125 (exact)
    const int score_grid = (NROWS * 32 + 255) / 256;

    // Layer 1
    gemm_k<<<gemm_grid, 128>>>(x, w1, hid);
    scores_k<<<score_grid, 256>>>(hid, ain1, aout1, sin_, sout_);
    agg_k<<<NROWS, 128>>>(hid, sin_, sout_, dst, adj, b1, h1);

    // Layer 2
    gemm_k<<<gemm_grid, 128>>>(h1, w2, hid);
    scores_k<<<score_grid, 256>>>(hid, ain2, aout2, sin_, sout_);
    agg_k<<<NROWS, 128>>>(hid, sin_, sout_, dst, adj, b2, out);
}

// round 2
// speedup vs baseline: 1.2923x; 1.2923x over previous
#include <cuda_runtime.h>

#define NROWS 100000
#define D 128
#define KN 16

// Scratch (no allocations allowed).
__device__ float g_hid[NROWS * D];
__device__ float g_h1[NROWS * D];
__device__ float g_sin[NROWS];
__device__ float g_sout[NROWS];

// ---------------------------------------------------------------------------
// Packed f32x2 helpers (sm_10x): 2 FMAs per instruction on the fma pipe.
// ---------------------------------------------------------------------------
typedef unsigned long long u64;

static __device__ __forceinline__ u64 pk2(float lo, float hi) {
    u64 r; asm("mov.b64 %0, {%1, %2};" : "=l"(r) : "f"(lo), "f"(hi)); return r;
}
static __device__ __forceinline__ u64 dup2(float v) {
    u64 r; asm("mov.b64 %0, {%1, %1};" : "=l"(r) : "f"(v)); return r;
}
static __device__ __forceinline__ u64 fma2(u64 a, u64 b, u64 c) {
    u64 d; asm("fma.rn.f32x2 %0, %1, %2, %3;" : "=l"(d) : "l"(a), "l"(b), "l"(c)); return d;
}
static __device__ __forceinline__ void upk2(u64 v, float& lo, float& hi) {
    asm("mov.b64 {%0, %1}, %2;" : "=f"(lo), "=f"(hi) : "l"(v));
}

// ---------------------------------------------------------------------------
// Fused GEMM + attention-score dots.
// hid = X @ W  (X:[N,128], W:[128,128]); sin[i]=hid[i]·a_in; sout[i]=hid[i]·a_out.
// Block: 64 rows x 128 cols, 128 threads (4 warps). Warp: 16 rows x 128 cols.
// Thread: 16 rows x 4 cols, accumulators as 2x u64 (f32x2 col-pairs) per row.
// Per warp-k-pair: 16 broadcast LDS.64 (x) + 2 LDG.128 (W, L1-hit) + 64 f32x2.
// ---------------------------------------------------------------------------
__global__ __launch_bounds__(128) void gemm_fused_k(
    const float* __restrict__ X, const float* __restrict__ W,
    const float* __restrict__ a_in, const float* __restrict__ a_out,
    float* __restrict__ hid, float* __restrict__ sin_, float* __restrict__ sout_) {
    __shared__ float xs[64 * D];
    const int tx = threadIdx.x;
    const int row0 = blockIdx.x * 64;

    // Stage X tile (zero-pad rows past N): 2048 float4, 16 per thread.
    const float4* xsrc = (const float4*)X;
    float4* xd = (float4*)xs;
#pragma unroll
    for (int j = 0; j < 16; j++) {
        int i4 = tx + j * 128;
        int r = i4 >> 5;
        float4 v = make_float4(0.f, 0.f, 0.f, 0.f);
        if (row0 + r < NROWS) v = xsrc[(size_t)row0 * 32 + i4];
        xd[i4] = v;
    }
    __syncthreads();

    const int wid = tx >> 5, lane = tx & 31;
    const float* xw = xs + wid * 16 * D;

    u64 acc01[16], acc23[16];
    const u64 z = pk2(0.f, 0.f);
#pragma unroll
    for (int r = 0; r < 16; r++) { acc01[r] = z; acc23[r] = z; }

    const float4* W4 = (const float4*)W;
#pragma unroll 2
    for (int k = 0; k < D; k += 2) {
        float4 wa = W4[k * 32 + lane];
        float4 wb = W4[(k + 1) * 32 + lane];
        u64 wa01 = pk2(wa.x, wa.y), wa23 = pk2(wa.z, wa.w);
        u64 wb01 = pk2(wb.x, wb.y), wb23 = pk2(wb.z, wb.w);
#pragma unroll
        for (int r = 0; r < 16; r++) {
            float2 xv = *(const float2*)(xw + r * D + k);   // broadcast LDS.64
            u64 xa = dup2(xv.x), xb = dup2(xv.y);
            acc01[r] = fma2(xa, wa01, acc01[r]);
            acc23[r] = fma2(xa, wa23, acc23[r]);
            acc01[r] = fma2(xb, wb01, acc01[r]);
            acc23[r] = fma2(xb, wb23, acc23[r]);
        }
    }

    // Epilogue: store hid rows + fused score dots (warp shuffle reduce).
    const float4 ai = ((const float4*)a_in)[lane];
    const float4 ao = ((const float4*)a_out)[lane];
    float4* hid4 = (float4*)hid;
#pragma unroll
    for (int r = 0; r < 16; r++) {
        float a0, a1, a2, a3;
        upk2(acc01[r], a0, a1);
        upk2(acc23[r], a2, a3);
        float si = a0 * ai.x + a1 * ai.y + a2 * ai.z + a3 * ai.w;
        float so = a0 * ao.x + a1 * ao.y + a2 * ao.z + a3 * ao.w;
#pragma unroll
        for (int o = 16; o; o >>= 1) {
            si += __shfl_xor_sync(0xffffffffu, si, o);
            so += __shfl_xor_sync(0xffffffffu, so, o);
        }
        int row = row0 + wid * 16 + r;
        if (row < NROWS) {
            hid4[(size_t)row * 32 + lane] = make_float4(a0, a1, a2, a3);
            if (lane == 0) { sin_[row] = si; sout_[row] = so; }
        }
    }
}

// ---------------------------------------------------------------------------
// Softmax(K=16) + weighted neighbor aggregation + bias + ReLU.
// One warp per dst row: lanes 0-15 compute edge weights (width-16 shuffles),
// then all 32 lanes gather float4 columns; weights broadcast via shfl.
// No smem, no __syncthreads, 16 independent LDG.128 per warp in flight.
// ---------------------------------------------------------------------------
__global__ __launch_bounds__(128) void agg_k(
    const float* __restrict__ hid, const float* __restrict__ sin_,
    const float* __restrict__ sout_, const int* __restrict__ dst,
    const float* __restrict__ adj, const float* __restrict__ b,
    float* __restrict__ out) {
    const int row = blockIdx.x * 4 + (threadIdx.x >> 5);   // grid*4 == NROWS
    const int lane = threadIdx.x & 31;

    int dd = 0;
    float we = 0.f;
    if (lane < KN) {
        dd = dst[row * KN + lane];
        float e = sin_[row] + sout_[dd];
        e = e > 0.f ? e : 0.2f * e;                         // leaky_relu(0.2)
        float m = e;
#pragma unroll
        for (int o = 8; o; o >>= 1)
            m = fmaxf(m, __shfl_xor_sync(0xffffu, m, o, 16));
        float ex = __expf(e - m);
        float s = ex;
#pragma unroll
        for (int o = 8; o; o >>= 1)
            s += __shfl_xor_sync(0xffffu, s, o, 16);
        we = adj[row * KN + lane] * (ex / s);
    }

    const float4* hid4 = (const float4*)hid;
    float4 acc = ((const float4*)b)[lane];
#pragma unroll
    for (int k = 0; k < KN; k++) {
        int dk = __shfl_sync(0xffffffffu, dd, k);
        float wk = __shfl_sync(0xffffffffu, we, k);
        float4 v = hid4[(size_t)dk * 32 + lane];
        acc.x = fmaf(wk, v.x, acc.x);
        acc.y = fmaf(wk, v.y, acc.y);
        acc.z = fmaf(wk, v.z, acc.z);
        acc.w = fmaf(wk, v.w, acc.w);
    }
    ((float4*)out)[(size_t)row * 32 + lane] =
        make_float4(fmaxf(acc.x, 0.f), fmaxf(acc.y, 0.f),
                    fmaxf(acc.z, 0.f), fmaxf(acc.w, 0.f));
}

// ---------------------------------------------------------------------------

extern "C" void kernel_launch(void* const* d_in, const int* in_sizes, int n_in,
                              void* d_out, int out_size) {
    const float* x     = (const float*)d_in[0];
    const int*   dst   = (const int*)  d_in[1];
    const float* adj   = (const float*)d_in[2];
    const float* w1    = (const float*)d_in[3];
    const float* ain1  = (const float*)d_in[4];
    const float* aout1 = (const float*)d_in[5];
    const float* b1    = (const float*)d_in[6];
    const float* w2    = (const float*)d_in[7];
    const float* ain2  = (const float*)d_in[8];
    const float* aout2 = (const float*)d_in[9];
    const float* b2    = (const float*)d_in[10];
    float* out = (float*)d_out;

    float *hid, *h1, *sin_, *sout_;
    cudaGetSymbolAddress((void**)&hid,   g_hid);
    cudaGetSymbolAddress((void**)&h1,    g_h1);
    cudaGetSymbolAddress((void**)&sin_,  g_sin);
    cudaGetSymbolAddress((void**)&sout_, g_sout);

    const int gemm_grid = (NROWS + 63) / 64;   // 1563
    const int agg_grid  = NROWS / 4;           // 25000 (exact)

    // Layer 1
    gemm_fused_k<<<gemm_grid, 128>>>(x, w1, ain1, aout1, hid, sin_, sout_);
    agg_k<<<agg_grid, 128>>>(hid, sin_, sout_, dst, adj, b1, h1);

    // Layer 2
    gemm_fused_k<<<gemm_grid, 128>>>(h1, w2, ain2, aout2, hid, sin_, sout_);
    agg_k<<<agg_grid, 128>>>(hid, sin_, sout_, dst, adj, b2, out);
}

// round 4
// speedup vs baseline: 1.9490x; 1.5082x over previous
#include <cuda_runtime.h>

#define NROWS 100000
#define D 128
#define KN 16

// Scratch (no allocations allowed).
__device__ float g_hid[NROWS * D];
__device__ float g_h1[NROWS * D];
__device__ float g_sin[NROWS];
__device__ float g_sout[NROWS];

// Padded SMEM strides (floats) — conflict-free fragment loads.
#define WS_STRIDE 136
#define XS_STRIDE 132
#define WS_ELEMS  (D * WS_STRIDE)              // 17408
#define XS_ELEMS  (64 * XS_STRIDE)             // 8448
#define GEMM_SMEM ((WS_ELEMS + XS_ELEMS) * 4)  // 103424 B

static __device__ __forceinline__ unsigned to_tf32(float f) {
    unsigned r; asm("cvt.rna.tf32.f32 %0, %1;" : "=r"(r) : "f"(f)); return r;
}

static __device__ __forceinline__ void mma_tf32(
    float& c0, float& c1, float& c2, float& c3,
    unsigned a0, unsigned a1, unsigned a2, unsigned a3,
    unsigned b0, unsigned b1) {
    asm volatile(
        "mma.sync.aligned.m16n8k8.row.col.f32.tf32.tf32.f32 "
        "{%0,%1,%2,%3}, {%4,%5,%6,%7}, {%8,%9}, {%0,%1,%2,%3};"
        : "+f"(c0), "+f"(c1), "+f"(c2), "+f"(c3)
        : "r"(a0), "r"(a1), "r"(a2), "r"(a3), "r"(b0), "r"(b1));
}

// ---------------------------------------------------------------------------
// tf32 tensor-core GEMM + fused attention-score dots.
// Block: 128 threads (4 warps), 64 rows. Warp w: 64 rows x cols [w*32, w*32+32)
// via 4(m16) x 4(n8) mma.m16n8k8 tiles. Score dots reduced across warps in SMEM.
// ---------------------------------------------------------------------------
__global__ __launch_bounds__(128) void gemm_fused_k(
    const float* __restrict__ X, const float* __restrict__ W,
    const float* __restrict__ a_in, const float* __restrict__ a_out,
    float* __restrict__ hid, float* __restrict__ sin_, float* __restrict__ sout_) {
    extern __shared__ unsigned sm[];
    unsigned* ws = sm;                 // [128][WS_STRIDE]
    unsigned* xs = sm + WS_ELEMS;      // [64][XS_STRIDE]

    const int tx = threadIdx.x;
    const int row0 = blockIdx.x * 64;
    const int wid = tx >> 5, lane = tx & 31;
    const int lane4 = lane & 3, laneD4 = lane >> 2;

    // Stage W: 4096 float4, 32 per thread, cvt to tf32.
    const float4* W4 = (const float4*)W;
#pragma unroll
    for (int j = 0; j < 32; j++) {
        int idx = j * 128 + tx;
        int r = idx >> 5, c4 = idx & 31;
        float4 v = W4[idx];
        unsigned* d = ws + r * WS_STRIDE + c4 * 4;
        d[0] = to_tf32(v.x); d[1] = to_tf32(v.y);
        d[2] = to_tf32(v.z); d[3] = to_tf32(v.w);
    }
    // Stage X tile: 2048 float4, 16 per thread, zero-pad rows >= N.
    const float4* X4 = (const float4*)X;
#pragma unroll
    for (int j = 0; j < 16; j++) {
        int idx = j * 128 + tx;
        int r = idx >> 5, c4 = idx & 31;
        float4 v = make_float4(0.f, 0.f, 0.f, 0.f);
        if (row0 + r < NROWS) v = X4[(size_t)row0 * 32 + idx];
        unsigned* d = xs + r * XS_STRIDE + c4 * 4;
        d[0] = to_tf32(v.x); d[1] = to_tf32(v.y);
        d[2] = to_tf32(v.z); d[3] = to_tf32(v.w);
    }
    __syncthreads();

    float c[4][4][4];
#pragma unroll
    for (int mt = 0; mt < 4; mt++)
#pragma unroll
        for (int nt = 0; nt < 4; nt++)
#pragma unroll
            for (int j = 0; j < 4; j++) c[mt][nt][j] = 0.f;

#pragma unroll 2
    for (int k0 = 0; k0 < D; k0 += 8) {
        unsigned a[4][4];
#pragma unroll
        for (int mt = 0; mt < 4; mt++) {
            const unsigned* p = xs + (mt * 16 + laneD4) * XS_STRIDE + k0 + lane4;
            a[mt][0] = p[0];
            a[mt][1] = p[8 * XS_STRIDE];
            a[mt][2] = p[4];
            a[mt][3] = p[8 * XS_STRIDE + 4];
        }
        unsigned b[4][2];
#pragma unroll
        for (int nt = 0; nt < 4; nt++) {
            const unsigned* p = ws + (k0 + lane4) * WS_STRIDE + wid * 32 + nt * 8 + laneD4;
            b[nt][0] = p[0];
            b[nt][1] = p[4 * WS_STRIDE];
        }
#pragma unroll
        for (int mt = 0; mt < 4; mt++)
#pragma unroll
            for (int nt = 0; nt < 4; nt++)
                mma_tf32(c[mt][nt][0], c[mt][nt][1], c[mt][nt][2], c[mt][nt][3],
                         a[mt][0], a[mt][1], a[mt][2], a[mt][3],
                         b[nt][0], b[nt][1]);
    }

    // ---- Score dots: per-warp 32-col partials -> SMEM -> cross-warp sum ----
    float ai0[4], ai1[4], ao0[4], ao1[4];
#pragma unroll
    for (int nt = 0; nt < 4; nt++) {
        int cb = wid * 32 + nt * 8 + lane4 * 2;
        ai0[nt] = a_in[cb];  ai1[nt] = a_in[cb + 1];
        ao0[nt] = a_out[cb]; ao1[nt] = a_out[cb + 1];
    }

    __syncthreads();                    // done reading xs — reuse for reduction
    float* red = (float*)xs;            // [2][64 rows][4 warps] = 512 floats

#pragma unroll
    for (int mt = 0; mt < 4; mt++) {
        float si_lo = 0.f, si_hi = 0.f, so_lo = 0.f, so_hi = 0.f;
#pragma unroll
        for (int nt = 0; nt < 4; nt++) {
            si_lo += c[mt][nt][0] * ai0[nt] + c[mt][nt][1] * ai1[nt];
            si_hi += c[mt][nt][2] * ai0[nt] + c[mt][nt][3] * ai1[nt];
            so_lo += c[mt][nt][0] * ao0[nt] + c[mt][nt][1] * ao1[nt];
            so_hi += c[mt][nt][2] * ao0[nt] + c[mt][nt][3] * ao1[nt];
        }
#pragma unroll
        for (int o = 1; o <= 2; o <<= 1) {       // reduce over lane4 (cols)
            si_lo += __shfl_xor_sync(0xffffffffu, si_lo, o);
            si_hi += __shfl_xor_sync(0xffffffffu, si_hi, o);
            so_lo += __shfl_xor_sync(0xffffffffu, so_lo, o);
            so_hi += __shfl_xor_sync(0xffffffffu, so_hi, o);
        }
        if (lane4 == 0) {
            int rt = mt * 16 + laneD4;           // rows rt and rt+8 in tile
            red[rt * 4 + wid]             = si_lo;
            red[(rt + 8) * 4 + wid]       = si_hi;
            red[256 + rt * 4 + wid]       = so_lo;
            red[256 + (rt + 8) * 4 + wid] = so_hi;
        }
    }
    __syncthreads();
    if (tx < 64 && row0 + tx < NROWS) {
        float si = red[tx * 4] + red[tx * 4 + 1] + red[tx * 4 + 2] + red[tx * 4 + 3];
        float so = red[256 + tx * 4] + red[256 + tx * 4 + 1] +
                   red[256 + tx * 4 + 2] + red[256 + tx * 4 + 3];
        sin_[row0 + tx] = si;
        sout_[row0 + tx] = so;
    }

    // ---- Store hid fragments ----
    float2* hid2 = (float2*)hid;
#pragma unroll
    for (int mt = 0; mt < 4; mt++) {
        int r_lo = row0 + mt * 16 + laneD4;
        int r_hi = r_lo + 8;
        if (r_lo < NROWS) {
#pragma unroll
            for (int nt = 0; nt < 4; nt++) {
                int cb = wid * 32 + nt * 8 + lane4 * 2;
                hid2[(size_t)r_lo * 64 + (cb >> 1)] = make_float2(c[mt][nt][0], c[mt][nt][1]);
            }
        }
        if (r_hi < NROWS) {
#pragma unroll
            for (int nt = 0; nt < 4; nt++) {
                int cb = wid * 32 + nt * 8 + lane4 * 2;
                hid2[(size_t)r_hi * 64 + (cb >> 1)] = make_float2(c[mt][nt][2], c[mt][nt][3]);
            }
        }
    }
}

// ---------------------------------------------------------------------------
// Softmax(K=16) + weighted neighbor aggregation + bias + ReLU.
// One warp per dst row (at the gather-bandwidth floor).
// ---------------------------------------------------------------------------
__global__ __launch_bounds__(128) void agg_k(
    const float* __restrict__ hid, const float* __restrict__ sin_,
    const float* __restrict__ sout_, const int* __restrict__ dst,
    const float* __restrict__ adj, const float* __restrict__ b,
    float* __restrict__ out) {
    const int row = blockIdx.x * 4 + (threadIdx.x >> 5);
    const int lane = threadIdx.x & 31;

    int dd = 0;
    float we = 0.f;
    if (lane < KN) {
        dd = dst[row * KN + lane];
        float e = sin_[row] + sout_[dd];
        e = e > 0.f ? e : 0.2f * e;
        float m = e;
#pragma unroll
        for (int o = 8; o; o >>= 1)
            m = fmaxf(m, __shfl_xor_sync(0xffffu, m, o, 16));
        float ex = __expf(e - m);
        float s = ex;
#pragma unroll
        for (int o = 8; o; o >>= 1)
            s += __shfl_xor_sync(0xffffu, s, o, 16);
        we = adj[row * KN + lane] * (ex / s);
    }

    const float4* hid4 = (const float4*)hid;
    float4 acc = ((const float4*)b)[lane];
#pragma unroll
    for (int k = 0; k < KN; k++) {
        int dk = __shfl_sync(0xffffffffu, dd, k);
        float wk = __shfl_sync(0xffffffffu, we, k);
        float4 v = hid4[(size_t)dk * 32 + lane];
        acc.x = fmaf(wk, v.x, acc.x);
        acc.y = fmaf(wk, v.y, acc.y);
        acc.z = fmaf(wk, v.z, acc.z);
        acc.w = fmaf(wk, v.w, acc.w);
    }
    ((float4*)out)[(size_t)row * 32 + lane] =
        make_float4(fmaxf(acc.x, 0.f), fmaxf(acc.y, 0.f),
                    fmaxf(acc.z, 0.f), fmaxf(acc.w, 0.f));
}

// ---------------------------------------------------------------------------

extern "C" void kernel_launch(void* const* d_in, const int* in_sizes, int n_in,
                              void* d_out, int out_size) {
    const float* x     = (const float*)d_in[0];
    const int*   dst   = (const int*)  d_in[1];
    const float* adj   = (const float*)d_in[2];
    const float* w1    = (const float*)d_in[3];
    const float* ain1  = (const float*)d_in[4];
    const float* aout1 = (const float*)d_in[5];
    const float* b1    = (const float*)d_in[6];
    const float* w2    = (const float*)d_in[7];
    const float* ain2  = (const float*)d_in[8];
    const float* aout2 = (const float*)d_in[9];
    const float* b2    = (const float*)d_in[10];
    float* out = (float*)d_out;

    float *hid, *h1, *sin_, *sout_;
    cudaGetSymbolAddress((void**)&hid,   g_hid);
    cudaGetSymbolAddress((void**)&h1,    g_h1);
    cudaGetSymbolAddress((void**)&sin_,  g_sin);
    cudaGetSymbolAddress((void**)&sout_, g_sout);

    static bool attr_set = false;
    if (!attr_set) {
        cudaFuncSetAttribute(gemm_fused_k,
                             cudaFuncAttributeMaxDynamicSharedMemorySize, GEMM_SMEM);
        attr_set = true;
    }

    const int gemm_grid = (NROWS + 63) / 64;   // 1563
    const int agg_grid  = NROWS / 4;           // 25000

    // Layer 1
    gemm_fused_k<<<gemm_grid, 128, GEMM_SMEM>>>(x, w1, ain1, aout1, hid, sin_, sout_);
    agg_k<<<agg_grid, 128>>>(hid, sin_, sout_, dst, adj, b1, h1);

    // Layer 2
    gemm_fused_k<<<gemm_grid, 128, GEMM_SMEM>>>(h1, w2, ain2, aout2, hid, sin_, sout_);
    agg_k<<<agg_grid, 128>>>(hid, sin_, sout_, dst, adj, b2, out);
}

// round 5
// speedup vs baseline: 2.2008x; 1.1292x over previous
#include <cuda_runtime.h>
#include <cuda_fp16.h>

#define NROWS 100000
#define D 128
#define KN 16

// Scratch (no allocations allowed).
__device__ __half g_hidh[NROWS * D];   // fp16 gather copy of GEMM output
__device__ float  g_h1[NROWS * D];     // layer-1 activation (fp32, layer-2 input)
__device__ float  g_sin[NROWS];
__device__ float  g_sout[NROWS];

// Padded SMEM strides (floats) — conflict-free fragment loads.
#define WS_STRIDE 136
#define XS_STRIDE 132
#define WS_ELEMS  (D * WS_STRIDE)              // 17408
#define XS_ELEMS  (64 * XS_STRIDE)             // 8448
#define GEMM_SMEM ((WS_ELEMS + XS_ELEMS) * 4)  // 103424 B

static __device__ __forceinline__ unsigned to_tf32(float f) {
    unsigned r; asm("cvt.rna.tf32.f32 %0, %1;" : "=r"(r) : "f"(f)); return r;
}

static __device__ __forceinline__ void mma_tf32(
    float& c0, float& c1, float& c2, float& c3,
    unsigned a0, unsigned a1, unsigned a2, unsigned a3,
    unsigned b0, unsigned b1) {
    asm volatile(
        "mma.sync.aligned.m16n8k8.row.col.f32.tf32.tf32.f32 "
        "{%0,%1,%2,%3}, {%4,%5,%6,%7}, {%8,%9}, {%0,%1,%2,%3};"
        : "+f"(c0), "+f"(c1), "+f"(c2), "+f"(c3)
        : "r"(a0), "r"(a1), "r"(a2), "r"(a3), "r"(b0), "r"(b1));
}

// ---------------------------------------------------------------------------
// tf32 tensor-core GEMM + fused attention-score dots.
// Block: 128 threads (4 warps), 64 rows. Warp w: 64 rows x cols [w*32, w*32+32)
// via 4(m16) x 4(n8) mma.m16n8k8 tiles. Scores reduced across warps in SMEM.
// hid is written out in fp16 ONLY (the aggregation kernel is its sole reader).
// ---------------------------------------------------------------------------
__global__ __launch_bounds__(128) void gemm_fused_k(
    const float* __restrict__ X, const float* __restrict__ W,
    const float* __restrict__ a_in, const float* __restrict__ a_out,
    __half* __restrict__ hidh, float* __restrict__ sin_, float* __restrict__ sout_) {
    extern __shared__ unsigned sm[];
    unsigned* ws = sm;                 // [128][WS_STRIDE]
    unsigned* xs = sm + WS_ELEMS;      // [64][XS_STRIDE]

    const int tx = threadIdx.x;
    const int row0 = blockIdx.x * 64;
    const int wid = tx >> 5, lane = tx & 31;
    const int lane4 = lane & 3, laneD4 = lane >> 2;

    // Stage W: 4096 float4, 32 per thread, cvt to tf32.
    const float4* W4 = (const float4*)W;
#pragma unroll
    for (int j = 0; j < 32; j++) {
        int idx = j * 128 + tx;
        int r = idx >> 5, c4 = idx & 31;
        float4 v = W4[idx];
        unsigned* d = ws + r * WS_STRIDE + c4 * 4;
        d[0] = to_tf32(v.x); d[1] = to_tf32(v.y);
        d[2] = to_tf32(v.z); d[3] = to_tf32(v.w);
    }
    // Stage X tile: 2048 float4, 16 per thread, zero-pad rows >= N.
    const float4* X4 = (const float4*)X;
#pragma unroll
    for (int j = 0; j < 16; j++) {
        int idx = j * 128 + tx;
        int r = idx >> 5, c4 = idx & 31;
        float4 v = make_float4(0.f, 0.f, 0.f, 0.f);
        if (row0 + r < NROWS) v = X4[(size_t)row0 * 32 + idx];
        unsigned* d = xs + r * XS_STRIDE + c4 * 4;
        d[0] = to_tf32(v.x); d[1] = to_tf32(v.y);
        d[2] = to_tf32(v.z); d[3] = to_tf32(v.w);
    }
    __syncthreads();

    float c[4][4][4];
#pragma unroll
    for (int mt = 0; mt < 4; mt++)
#pragma unroll
        for (int nt = 0; nt < 4; nt++)
#pragma unroll
            for (int j = 0; j < 4; j++) c[mt][nt][j] = 0.f;

#pragma unroll 2
    for (int k0 = 0; k0 < D; k0 += 8) {
        unsigned a[4][4];
#pragma unroll
        for (int mt = 0; mt < 4; mt++) {
            const unsigned* p = xs + (mt * 16 + laneD4) * XS_STRIDE + k0 + lane4;
            a[mt][0] = p[0];
            a[mt][1] = p[8 * XS_STRIDE];
            a[mt][2] = p[4];
            a[mt][3] = p[8 * XS_STRIDE + 4];
        }
        unsigned b[4][2];
#pragma unroll
        for (int nt = 0; nt < 4; nt++) {
            const unsigned* p = ws + (k0 + lane4) * WS_STRIDE + wid * 32 + nt * 8 + laneD4;
            b[nt][0] = p[0];
            b[nt][1] = p[4 * WS_STRIDE];
        }
#pragma unroll
        for (int mt = 0; mt < 4; mt++)
#pragma unroll
            for (int nt = 0; nt < 4; nt++)
                mma_tf32(c[mt][nt][0], c[mt][nt][1], c[mt][nt][2], c[mt][nt][3],
                         a[mt][0], a[mt][1], a[mt][2], a[mt][3],
                         b[nt][0], b[nt][1]);
    }

    // ---- Score dots (fp32): per-warp partials -> SMEM -> cross-warp sum ----
    float ai0[4], ai1[4], ao0[4], ao1[4];
#pragma unroll
    for (int nt = 0; nt < 4; nt++) {
        int cb = wid * 32 + nt * 8 + lane4 * 2;
        ai0[nt] = a_in[cb];  ai1[nt] = a_in[cb + 1];
        ao0[nt] = a_out[cb]; ao1[nt] = a_out[cb + 1];
    }

    __syncthreads();                    // done reading xs — reuse for reduction
    float* red = (float*)xs;            // [2][64 rows][4 warps] = 512 floats

#pragma unroll
    for (int mt = 0; mt < 4; mt++) {
        float si_lo = 0.f, si_hi = 0.f, so_lo = 0.f, so_hi = 0.f;
#pragma unroll
        for (int nt = 0; nt < 4; nt++) {
            si_lo += c[mt][nt][0] * ai0[nt] + c[mt][nt][1] * ai1[nt];
            si_hi += c[mt][nt][2] * ai0[nt] + c[mt][nt][3] * ai1[nt];
            so_lo += c[mt][nt][0] * ao0[nt] + c[mt][nt][1] * ao1[nt];
            so_hi += c[mt][nt][2] * ao0[nt] + c[mt][nt][3] * ao1[nt];
        }
#pragma unroll
        for (int o = 1; o <= 2; o <<= 1) {       // reduce over lane4 (cols)
            si_lo += __shfl_xor_sync(0xffffffffu, si_lo, o);
            si_hi += __shfl_xor_sync(0xffffffffu, si_hi, o);
            so_lo += __shfl_xor_sync(0xffffffffu, so_lo, o);
            so_hi += __shfl_xor_sync(0xffffffffu, so_hi, o);
        }
        if (lane4 == 0) {
            int rt = mt * 16 + laneD4;
            red[rt * 4 + wid]             = si_lo;
            red[(rt + 8) * 4 + wid]       = si_hi;
            red[256 + rt * 4 + wid]       = so_lo;
            red[256 + (rt + 8) * 4 + wid] = so_hi;
        }
    }
    __syncthreads();
    if (tx < 64 && row0 + tx < NROWS) {
        float si = red[tx * 4] + red[tx * 4 + 1] + red[tx * 4 + 2] + red[tx * 4 + 3];
        float so = red[256 + tx * 4] + red[256 + tx * 4 + 1] +
                   red[256 + tx * 4 + 2] + red[256 + tx * 4 + 3];
        sin_[row0 + tx] = si;
        sout_[row0 + tx] = so;
    }

    // ---- Store hid fragments as fp16 (half2 per col-pair) ----
    __half2* hidh2 = (__half2*)hidh;
#pragma unroll
    for (int mt = 0; mt < 4; mt++) {
        int r_lo = row0 + mt * 16 + laneD4;
        int r_hi = r_lo + 8;
        if (r_lo < NROWS) {
#pragma unroll
            for (int nt = 0; nt < 4; nt++) {
                int cb = wid * 32 + nt * 8 + lane4 * 2;
                hidh2[(size_t)r_lo * 64 + (cb >> 1)] =
                    __floats2half2_rn(c[mt][nt][0], c[mt][nt][1]);
            }
        }
        if (r_hi < NROWS) {
#pragma unroll
            for (int nt = 0; nt < 4; nt++) {
                int cb = wid * 32 + nt * 8 + lane4 * 2;
                hidh2[(size_t)r_hi * 64 + (cb >> 1)] =
                    __floats2half2_rn(c[mt][nt][2], c[mt][nt][3]);
            }
        }
    }
}

// ---------------------------------------------------------------------------
// Softmax(K=16) + weighted neighbor aggregation + bias + ReLU.
// One warp per dst row. Gathers fp16 rows (256 B/row: uint2 per lane),
// accumulates fp32. L2 gather traffic halved vs fp32.
// ---------------------------------------------------------------------------
__global__ __launch_bounds__(128) void agg_k(
    const __half* __restrict__ hidh, const float* __restrict__ sin_,
    const float* __restrict__ sout_, const int* __restrict__ dst,
    const float* __restrict__ adj, const float* __restrict__ b,
    float* __restrict__ out) {
    const int row = blockIdx.x * 4 + (threadIdx.x >> 5);
    const int lane = threadIdx.x & 31;

    int dd = 0;
    float we = 0.f;
    if (lane < KN) {
        dd = dst[row * KN + lane];
        float e = sin_[row] + sout_[dd];
        e = e > 0.f ? e : 0.2f * e;
        float m = e;
#pragma unroll
        for (int o = 8; o; o >>= 1)
            m = fmaxf(m, __shfl_xor_sync(0xffffu, m, o, 16));
        float ex = __expf(e - m);
        float s = ex;
#pragma unroll
        for (int o = 8; o; o >>= 1)
            s += __shfl_xor_sync(0xffffu, s, o, 16);
        we = adj[row * KN + lane] * (ex / s);
    }

    const uint2* hh = (const uint2*)hidh;      // 4 halves per uint2, 32 per row
    float4 acc = ((const float4*)b)[lane];
#pragma unroll
    for (int k = 0; k < KN; k++) {
        int dk = __shfl_sync(0xffffffffu, dd, k);
        float wk = __shfl_sync(0xffffffffu, we, k);
        uint2 v = hh[(size_t)dk * 32 + lane];
        float2 f0 = __half22float2(*(const __half2*)&v.x);
        float2 f1 = __half22float2(*(const __half2*)&v.y);
        acc.x = fmaf(wk, f0.x, acc.x);
        acc.y = fmaf(wk, f0.y, acc.y);
        acc.z = fmaf(wk, f1.x, acc.z);
        acc.w = fmaf(wk, f1.y, acc.w);
    }
    ((float4*)out)[(size_t)row * 32 + lane] =
        make_float4(fmaxf(acc.x, 0.f), fmaxf(acc.y, 0.f),
                    fmaxf(acc.z, 0.f), fmaxf(acc.w, 0.f));
}

// ---------------------------------------------------------------------------

extern "C" void kernel_launch(void* const* d_in, const int* in_sizes, int n_in,
                              void* d_out, int out_size) {
    const float* x     = (const float*)d_in[0];
    const int*   dst   = (const int*)  d_in[1];
    const float* adj   = (const float*)d_in[2];
    const float* w1    = (const float*)d_in[3];
    const float* ain1  = (const float*)d_in[4];
    const float* aout1 = (const float*)d_in[5];
    const float* b1    = (const float*)d_in[6];
    const float* w2    = (const float*)d_in[7];
    const float* ain2  = (const float*)d_in[8];
    const float* aout2 = (const float*)d_in[9];
    const float* b2    = (const float*)d_in[10];
    float* out = (float*)d_out;

    __half* hidh;
    float *h1, *sin_, *sout_;
    cudaGetSymbolAddress((void**)&hidh,  g_hidh);
    cudaGetSymbolAddress((void**)&h1,    g_h1);
    cudaGetSymbolAddress((void**)&sin_,  g_sin);
    cudaGetSymbolAddress((void**)&sout_, g_sout);

    static bool attr_set = false;
    if (!attr_set) {
        cudaFuncSetAttribute(gemm_fused_k,
                             cudaFuncAttributeMaxDynamicSharedMemorySize, GEMM_SMEM);
        attr_set = true;
    }

    const int gemm_grid = (NROWS + 63) / 64;   // 1563
    const int agg_grid  = NROWS / 4;           // 25000

    // Layer 1
    gemm_fused_k<<<gemm_grid, 128, GEMM_SMEM>>>(x, w1, ain1, aout1, hidh, sin_, sout_);
    agg_k<<<agg_grid, 128>>>(hidh, sin_, sout_, dst, adj, b1, h1);

    // Layer 2
    gemm_fused_k<<<gemm_grid, 128, GEMM_SMEM>>>(h1, w2, ain2, aout2, hidh, sin_, sout_);
    agg_k<<<agg_grid, 128>>>(hidh, sin_, sout_, dst, adj, b2, out);
}

// round 10
// speedup vs baseline: 2.7845x; 1.2652x over previous
#include <cuda_runtime.h>
#include <cuda_fp16.h>

#define NROWS 100000
#define D 128
#define KN 16

// Scratch (no allocations allowed).
__device__ __half g_hidh[NROWS * D];   // fp16 GEMM output (gather source)
__device__ __half g_h1h[NROWS * D];    // fp16 layer-1 activation (layer-2 input)
__device__ float  g_sin[NROWS];
__device__ float  g_sout[NROWS];

// SMEM: W tile 128 rows x 256B at 0; X tile 64 rows x 256B at 32768. 48KB total.
#define WOFF 0
#define XOFF 32768
#define GEMM_SMEM 49152

static __device__ __forceinline__ unsigned pack_h2(float a, float b) {
    __half2 h = __floats2half2_rn(a, b);
    return *(unsigned*)&h;
}

static __device__ __forceinline__ unsigned smem_u32(const void* p) {
    unsigned a;
    asm("{ .reg .u64 t; cvta.to.shared.u64 t, %1; cvt.u32.u64 %0, t; }"
        : "=r"(a) : "l"(p));
    return a;
}

// Load one 16B granule (8 halves) = X[row][g*8 .. g*8+7], converting if fp32.
static __device__ __forceinline__ uint4 load_gran(const float* X, int row, int g) {
    const float4* s = (const float4*)(X + (size_t)row * D + g * 8);
    float4 v0 = s[0], v1 = s[1];
    uint4 h;
    h.x = pack_h2(v0.x, v0.y); h.y = pack_h2(v0.z, v0.w);
    h.z = pack_h2(v1.x, v1.y); h.w = pack_h2(v1.z, v1.w);
    return h;
}
static __device__ __forceinline__ uint4 load_gran(const __half* X, int row, int g) {
    return ((const uint4*)(X + (size_t)row * D))[g];
}

static __device__ __forceinline__ void ldsm_x4(unsigned* r, unsigned addr) {
    asm volatile("ldmatrix.sync.aligned.m8n8.x4.shared.b16 {%0,%1,%2,%3}, [%4];"
        : "=r"(r[0]), "=r"(r[1]), "=r"(r[2]), "=r"(r[3]) : "r"(addr));
}
static __device__ __forceinline__ void ldsm_x2t(unsigned* r, unsigned addr) {
    asm volatile("ldmatrix.sync.aligned.m8n8.x2.trans.shared.b16 {%0,%1}, [%2];"
        : "=r"(r[0]), "=r"(r[1]) : "r"(addr));
}
static __device__ __forceinline__ void mma_f16(
    float& c0, float& c1, float& c2, float& c3,
    unsigned a0, unsigned a1, unsigned a2, unsigned a3,
    unsigned b0, unsigned b1) {
    asm volatile(
        "mma.sync.aligned.m16n8k16.row.col.f32.f16.f16.f32 "
        "{%0,%1,%2,%3}, {%4,%5,%6,%7}, {%8,%9}, {%0,%1,%2,%3};"
        : "+f"(c0), "+f"(c1), "+f"(c2), "+f"(c3)
        : "r"(a0), "r"(a1), "r"(a2), "r"(a3), "r"(b0), "r"(b1));
}

// ---------------------------------------------------------------------------
// fp16 tensor-core GEMM + fused attention-score dots.
// Block: 128 thr (4 warps), 64 rows. Warp w: 64 rows x cols [w*32, w*32+32)
// via 4(m16) x 4(n8) mma.m16n8k16. X/W staged fp16 in SMEM (256B rows,
// 16B-granule swizzle g ^= row&7); fragments via ldmatrix (.trans for B).
// ---------------------------------------------------------------------------
template <typename InT>
__global__ __launch_bounds__(128, 4) void gemm_fused_k(
    const InT* __restrict__ X, const float* __restrict__ W,
    const float* __restrict__ a_in, const float* __restrict__ a_out,
    __half* __restrict__ hidh, float* __restrict__ sin_, float* __restrict__ sout_) {
    extern __shared__ __align__(16) unsigned char smem[];
    const unsigned smem_u = smem_u32(smem);

    const int tx = threadIdx.x;
    const int row0 = blockIdx.x * 64;
    const int wid = tx >> 5, lane = tx & 31;

    // Stage W: 2048 granules, 16 per thread.
#pragma unroll
    for (int it = 0; it < 16; it++) {
        int gi = it * 128 + tx;
        int r = gi >> 4, g = gi & 15;
        uint4 h = load_gran(W, r, g);
        *(uint4*)(smem + WOFF + r * 256 + ((g ^ (r & 7)) << 4)) = h;
    }
    // Stage X tile: 1024 granules, 8 per thread; zero-pad rows >= N.
#pragma unroll
    for (int it = 0; it < 8; it++) {
        int gi = it * 128 + tx;
        int r = gi >> 4, g = gi & 15;
        uint4 h = make_uint4(0u, 0u, 0u, 0u);
        if (row0 + r < NROWS) h = load_gran(X, row0 + r, g);
        *(uint4*)(smem + XOFF + r * 256 + ((g ^ (r & 7)) << 4)) = h;
    }
    __syncthreads();

    // Per-lane ldmatrix addressing.
    const int l15 = lane & 15;
    const int aRow = (lane & 7) + ((lane >> 3) & 1) * 8;   // row within m16 tile
    const int aGsel = lane >> 4;                           // k granule select
    const int aR7 = aRow & 7;
    unsigned bBase[4];
#pragma unroll
    for (int nt = 0; nt < 4; nt++)
        bBase[nt] = smem_u + WOFF + l15 * 256 + (((wid * 4 + nt) ^ (l15 & 7)) << 4);
    const unsigned aBase = smem_u + XOFF + aRow * 256;

    float c[4][4][4];
#pragma unroll
    for (int mt = 0; mt < 4; mt++)
#pragma unroll
        for (int nt = 0; nt < 4; nt++)
#pragma unroll
            for (int j = 0; j < 4; j++) c[mt][nt][j] = 0.f;

#pragma unroll
    for (int k0 = 0; k0 < D; k0 += 16) {
        const int kg = k0 >> 3;                    // even
        const unsigned ag = (unsigned)(((kg + aGsel) ^ aR7) << 4);
        unsigned a[4][4], b[4][2];
#pragma unroll
        for (int mt = 0; mt < 4; mt++)
            ldsm_x4(a[mt], aBase + mt * 4096 + ag);
#pragma unroll
        for (int nt = 0; nt < 4; nt++)
            ldsm_x2t(b[nt], bBase[nt] + k0 * 256);
#pragma unroll
        for (int mt = 0; mt < 4; mt++)
#pragma unroll
            for (int nt = 0; nt < 4; nt++)
                mma_f16(c[mt][nt][0], c[mt][nt][1], c[mt][nt][2], c[mt][nt][3],
                        a[mt][0], a[mt][1], a[mt][2], a[mt][3],
                        b[nt][0], b[nt][1]);
    }

    // ---- Score dots (fp32): per-warp partials -> SMEM -> cross-warp sum ----
    const int lane4 = lane & 3, laneD4 = lane >> 2;
    float ai0[4], ai1[4], ao0[4], ao1[4];
#pragma unroll
    for (int nt = 0; nt < 4; nt++) {
        int cb = wid * 32 + nt * 8 + lane4 * 2;
        ai0[nt] = a_in[cb];  ai1[nt] = a_in[cb + 1];
        ao0[nt] = a_out[cb]; ao1[nt] = a_out[cb + 1];
    }

    __syncthreads();                       // done reading xs — reuse for reduction
    float* red = (float*)(smem + XOFF);    // [2][64 rows][4 warps] = 512 floats

#pragma unroll
    for (int mt = 0; mt < 4; mt++) {
        float si_lo = 0.f, si_hi = 0.f, so_lo = 0.f, so_hi = 0.f;
#pragma unroll
        for (int nt = 0; nt < 4; nt++) {
            si_lo += c[mt][nt][0] * ai0[nt] + c[mt][nt][1] * ai1[nt];
            si_hi += c[mt][nt][2] * ai0[nt] + c[mt][nt][3] * ai1[nt];
            so_lo += c[mt][nt][0] * ao0[nt] + c[mt][nt][1] * ao1[nt];
            so_hi += c[mt][nt][2] * ao0[nt] + c[mt][nt][3] * ao1[nt];
        }
#pragma unroll
        for (int o = 1; o <= 2; o <<= 1) {         // reduce over lane4 (cols)
            si_lo += __shfl_xor_sync(0xffffffffu, si_lo, o);
            si_hi += __shfl_xor_sync(0xffffffffu, si_hi, o);
            so_lo += __shfl_xor_sync(0xffffffffu, so_lo, o);
            so_hi += __shfl_xor_sync(0xffffffffu, so_hi, o);
        }
        if (lane4 == 0) {
            int rt = mt * 16 + laneD4;
            red[rt * 4 + wid]             = si_lo;
            red[(rt + 8) * 4 + wid]       = si_hi;
            red[256 + rt * 4 + wid]       = so_lo;
            red[256 + (rt + 8) * 4 + wid] = so_hi;
        }
    }
    __syncthreads();
    if (tx < 64 && row0 + tx < NROWS) {
        float si = red[tx * 4] + red[tx * 4 + 1] + red[tx * 4 + 2] + red[tx * 4 + 3];
        float so = red[256 + tx * 4] + red[256 + tx * 4 + 1] +
                   red[256 + tx * 4 + 2] + red[256 + tx * 4 + 3];
        sin_[row0 + tx] = si;
        sout_[row0 + tx] = so;
    }

    // ---- Store hid fragments as fp16 (half2 per col-pair) ----
    unsigned* hidh2 = (unsigned*)hidh;
#pragma unroll
    for (int mt = 0; mt < 4; mt++) {
        int r_lo = row0 + mt * 16 + laneD4;
        int r_hi = r_lo + 8;
        if (r_lo < NROWS) {
#pragma unroll
            for (int nt = 0; nt < 4; nt++) {
                int cb = wid * 32 + nt * 8 + lane4 * 2;
                hidh2[(size_t)r_lo * 64 + (cb >> 1)] = pack_h2(c[mt][nt][0], c[mt][nt][1]);
            }
        }
        if (r_hi < NROWS) {
#pragma unroll
            for (int nt = 0; nt < 4; nt++) {
                int cb = wid * 32 + nt * 8 + lane4 * 2;
                hidh2[(size_t)r_hi * 64 + (cb >> 1)] = pack_h2(c[mt][nt][2], c[mt][nt][3]);
            }
        }
    }
}

// ---------------------------------------------------------------------------
// Softmax(K=16) + weighted neighbor aggregation + bias + ReLU.
// One warp per dst row; fp16 gathers (256B/row), fp32 accumulate.
// OutT = __half for layer 1 (feeds fp16 GEMM), float for the final output.
// ---------------------------------------------------------------------------
template <typename OutT>
__global__ __launch_bounds__(128) void agg_k(
    const __half* __restrict__ hidh, const float* __restrict__ sin_,
    const float* __restrict__ sout_, const int* __restrict__ dst,
    const float* __restrict__ adj, const float* __restrict__ b,
    OutT* __restrict__ out) {
    const int row = blockIdx.x * 4 + (threadIdx.x >> 5);
    const int lane = threadIdx.x & 31;

    int dd = 0;
    float we = 0.f;
    if (lane < KN) {
        dd = dst[row * KN + lane];
        float e = sin_[row] + sout_[dd];
        e = e > 0.f ? e : 0.2f * e;
        float m = e;
#pragma unroll
        for (int o = 8; o; o >>= 1)
            m = fmaxf(m, __shfl_xor_sync(0xffffu, m, o, 16));
        float ex = __expf(e - m);
        float s = ex;
#pragma unroll
        for (int o = 8; o; o >>= 1)
            s += __shfl_xor_sync(0xffffu, s, o, 16);
        we = adj[row * KN + lane] * (ex / s);
    }

    const uint2* hh = (const uint2*)hidh;      // 4 halves per uint2, 32 per row
    float4 acc = ((const float4*)b)[lane];
#pragma unroll
    for (int k = 0; k < KN; k++) {
        unsigned dk = (unsigned)__shfl_sync(0xffffffffu, dd, k);
        float wk = __shfl_sync(0xffffffffu, we, k);
        uint2 v = hh[dk * 32u + (unsigned)lane];   // 32-bit offset arithmetic
        float2 f0 = __half22float2(*(const __half2*)&v.x);
        float2 f1 = __half22float2(*(const __half2*)&v.y);
        acc.x = fmaf(wk, f0.x, acc.x);
        acc.y = fmaf(wk, f0.y, acc.y);
        acc.z = fmaf(wk, f1.x, acc.z);
        acc.w = fmaf(wk, f1.y, acc.w);
    }
    acc.x = fmaxf(acc.x, 0.f); acc.y = fmaxf(acc.y, 0.f);
    acc.z = fmaxf(acc.z, 0.f); acc.w = fmaxf(acc.w, 0.f);
    if constexpr (sizeof(OutT) == 2) {
        uint2 p;
        p.x = pack_h2(acc.x, acc.y);
        p.y = pack_h2(acc.z, acc.w);
        ((uint2*)out)[(size_t)row * 32 + lane] = p;
    } else {
        ((float4*)out)[(size_t)row * 32 + lane] = acc;
    }
}

// ---------------------------------------------------------------------------

extern "C" void kernel_launch(void* const* d_in, const int* in_sizes, int n_in,
                              void* d_out, int out_size) {
    const float* x     = (const float*)d_in[0];
    const int*   dst   = (const int*)  d_in[1];
    const float* adj   = (const float*)d_in[2];
    const float* w1    = (const float*)d_in[3];
    const float* ain1  = (const float*)d_in[4];
    const float* aout1 = (const float*)d_in[5];
    const float* b1    = (const float*)d_in[6];
    const float* w2    = (const float*)d_in[7];
    const float* ain2  = (const float*)d_in[8];
    const float* aout2 = (const float*)d_in[9];
    const float* b2    = (const float*)d_in[10];
    float* out = (float*)d_out;

    __half *hidh, *h1h;
    float *sin_, *sout_;
    cudaGetSymbolAddress((void**)&hidh,  g_hidh);
    cudaGetSymbolAddress((void**)&h1h,   g_h1h);
    cudaGetSymbolAddress((void**)&sin_,  g_sin);
    cudaGetSymbolAddress((void**)&sout_, g_sout);

    static bool attr_set = false;
    if (!attr_set) {
        cudaFuncSetAttribute(gemm_fused_k<float>,
                             cudaFuncAttributeMaxDynamicSharedMemorySize, GEMM_SMEM);
        cudaFuncSetAttribute(gemm_fused_k<__half>,
                             cudaFuncAttributeMaxDynamicSharedMemorySize, GEMM_SMEM);
        attr_set = true;
    }

    const int gemm_grid = (NROWS + 63) / 64;   // 1563
    const int agg_grid  = NROWS / 4;           // 25000

    // Layer 1
    gemm_fused_k<float><<<gemm_grid, 128, GEMM_SMEM>>>(x, w1, ain1, aout1, hidh, sin_, sout_);
    agg_k<__half><<<agg_grid, 128>>>(hidh, sin_, sout_, dst, adj, b1, h1h);

    // Layer 2
    gemm_fused_k<__half><<<gemm_grid, 128, GEMM_SMEM>>>(h1h, w2, ain2, aout2, hidh, sin_, sout_);
    agg_k<float><<<agg_grid, 128>>>(hidh, sin_, sout_, dst, adj, b2, out);
}